// round 12
// baseline (speedup 1.0000x reference)
#include <cuda_runtime.h>
#include <math.h>

#define B_ 65536
typedef unsigned long long u64;
typedef ulonglong2 u64x2;

// ---------------- f32x2 helpers (FFMA2 only reachable via PTX) --------------
__device__ __forceinline__ u64 fma2(u64 w, u64 a, u64 c) {
    u64 d; asm("fma.rn.f32x2 %0, %1, %2, %3;" : "=l"(d) : "l"(w), "l"(a), "l"(c));
    return d;
}
__device__ __forceinline__ u64 pack2(float x, float y) {
    u64 d; asm("mov.b64 %0, {%1, %2};" : "=l"(d)
               : "r"(__float_as_uint(x)), "r"(__float_as_uint(y)));
    return d;
}
__device__ __forceinline__ float lo32(u64 v) { return __uint_as_float((unsigned)v); }
__device__ __forceinline__ float hi32(u64 v) { return __uint_as_float((unsigned)(v >> 32)); }
__device__ __forceinline__ u64 ld2(const float* p) { return *reinterpret_cast<const u64*>(p); }
__device__ __forceinline__ void st2(float* p, u64 v) { *reinterpret_cast<u64*>(p) = v; }

__device__ __forceinline__ float4 relu4(float4 v) {
    return make_float4(fmaxf(v.x, 0.f), fmaxf(v.y, 0.f),
                       fmaxf(v.z, 0.f), fmaxf(v.w, 0.f));
}

// ---------------- scratch (device globals; no allocations) ------------------
__device__ float g_dataT[512u * B_];   // [s][b]
__device__ float g_mag  [516u * B_];   // [(f*4+t)][b]   f<129, t<4
__device__ float g_out1 [512u * B_];   // [(c*4+t)][b]   c<128
__device__ float g_out2 [128u * B_];   // [(c*2+t)][b]   c<64
__device__ float g_out3 [ 64u * B_];   // [c][b]
__device__ float g_out4 [128u * B_];   // [c][b]
__device__ float g_gates[512u * B_];   // [g][b]

// ---- CT=16 channels (8 f32x2 pairs) x BT=8 batches core --------------------
// acc[m][p]: f32x2 = output channels (c0+2m, c0+2m+1), batch b+p.
__device__ __forceinline__ void dup8v(float4 v0, float4 v1, u64 (&A)[8]) {
    A[0] = pack2(v0.x, v0.x); A[1] = pack2(v0.y, v0.y);
    A[2] = pack2(v0.z, v0.z); A[3] = pack2(v0.w, v0.w);
    A[4] = pack2(v1.x, v1.x); A[5] = pack2(v1.y, v1.y);
    A[6] = pack2(v1.z, v1.z); A[7] = pack2(v1.w, v1.w);
}
__device__ __forceinline__ void tap_row(const float* __restrict__ wrow,
                                        const float* __restrict__ act,
                                        u64 (&acc)[8][8]) {
    float4 v0 = *reinterpret_cast<const float4*>(act);
    float4 v1 = *reinterpret_cast<const float4*>(act + 4);
    u64 A[8];
    dup8v(v0, v1, A);
#pragma unroll
    for (int q = 0; q < 4; q++) {
        u64x2 W = *reinterpret_cast<const u64x2*>(wrow + 4 * q);
#pragma unroll
        for (int p = 0; p < 8; p++) {
            acc[2*q  ][p] = fma2(W.x, A[p], acc[2*q  ][p]);
            acc[2*q+1][p] = fma2(W.y, A[p], acc[2*q+1][p]);
        }
    }
}
__device__ __forceinline__ void tap_v(const float* __restrict__ wrow,
                                      float4 v0, float4 v1, u64 (&acc)[8][8]) {
    u64 A[8];
    dup8v(v0, v1, A);
#pragma unroll
    for (int q = 0; q < 4; q++) {
        u64x2 W = *reinterpret_cast<const u64x2*>(wrow + 4 * q);
#pragma unroll
        for (int p = 0; p < 8; p++) {
            acc[2*q  ][p] = fma2(W.x, A[p], acc[2*q  ][p]);
            acc[2*q+1][p] = fma2(W.y, A[p], acc[2*q+1][p]);
        }
    }
}
__device__ __forceinline__ void init_bias8(u64 (&acc)[8][8],
                                           const float* bias, int c0) {
#pragma unroll
    for (int m = 0; m < 8; m++) {
        u64 bv = pack2(bias[c0 + 2 * m], bias[c0 + 2 * m + 1]);
#pragma unroll
        for (int p = 0; p < 8; p++) acc[m][p] = bv;
    }
}
__device__ __forceinline__ float4 lo4(const u64* a) {
    return make_float4(lo32(a[0]), lo32(a[1]), lo32(a[2]), lo32(a[3]));
}
__device__ __forceinline__ float4 hi4(const u64* a) {
    return make_float4(hi32(a[0]), hi32(a[1]), hi32(a[2]), hi32(a[3]));
}
// store channel pair (c, c+1) rows of 8 batches, optional relu
__device__ __forceinline__ void store_pair(float* dlo, float* dhi,
                                           const u64 (&a)[8], bool doRelu) {
    float4 L0 = lo4(a), L1 = lo4(a + 4), H0 = hi4(a), H1 = hi4(a + 4);
    if (doRelu) { L0 = relu4(L0); L1 = relu4(L1); H0 = relu4(H0); H1 = relu4(H1); }
    *reinterpret_cast<float4*>(dlo)     = L0;
    *reinterpret_cast<float4*>(dlo + 4) = L1;
    *reinterpret_cast<float4*>(dhi)     = H0;
    *reinterpret_cast<float4*>(dhi + 4) = H1;
}

// ---------------- K0: transpose data[B][512] -> dataT[512][B] ---------------
__global__ void k_transpose(const float* __restrict__ x) {
    __shared__ float tile[32][33];
    int b0 = blockIdx.x * 32, s0 = blockIdx.y * 32;
    int tx = threadIdx.x, ty = threadIdx.y;   // 32 x 8
#pragma unroll
    for (int i = 0; i < 32; i += 8)
        tile[ty + i][tx] = x[(size_t)(b0 + ty + i) * 512 + s0 + tx];
    __syncthreads();
#pragma unroll
    for (int i = 0; i < 32; i += 8)
        g_dataT[(size_t)(s0 + ty + i) * B_ + b0 + tx] = tile[tx][ty + i];
}

// ---------------- K1: STFT (stride 128) fused with mag ----------------------
// f32x2 lanes = (Real_f, Imag_f); 8 freqs/tile, 8 batches/thread.
//   t<3        : s = 128*t - 64 + kk  (kk < 64-128t would be zero -> skipped)
//   t=3, kk<192: s = 320 + kk ; kk>=192: s = 702 - kk (reflect)
__global__ __launch_bounds__(128, 3) void k_stft(const float* __restrict__ w) {
    const int t  = blockIdx.z;
    const int f0 = blockIdx.y * 8;
    const int b  = (blockIdx.x * 128 + threadIdx.x) * 8;
    __shared__ float ws[256][16];             // [kk][2*m + isImag]
    for (int idx = threadIdx.x; idx < 256 * 16; idx += 128) {
        int kk = idx >> 4, r = idx & 15, m = r >> 1, isI = r & 1;
        int f = f0 + m;
        ws[kk][r] = (f < 129) ? w[(f + 129 * isI) * 256 + kk] : 0.f;
    }
    u64 acc[8][8];
#pragma unroll
    for (int m = 0; m < 8; m++)
#pragma unroll
        for (int p = 0; p < 8; p++) acc[m][p] = 0ull;
    __syncthreads();

    const int kk0 = (t == 0) ? 64 : 0;        // skip zero-padded region
    for (int kk = kk0; kk < 256; kk++) {
        int s = (t < 3) ? (128 * t - 64 + kk)
                        : ((kk < 192) ? (320 + kk) : (702 - kk));
        tap_row(ws[kk], &g_dataT[(size_t)s * B_ + b], acc);
    }
#pragma unroll
    for (int m = 0; m < 8; m++) {
        int f = f0 + m;
        if (f < 129) {
            float mg[8];
#pragma unroll
            for (int p = 0; p < 8; p++) {
                float r = lo32(acc[m][p]), im = hi32(acc[m][p]);
                mg[p] = sqrtf(r * r + im * im);
            }
            float* dst = &g_mag[(size_t)(f * 4 + t) * B_ + b];
            *reinterpret_cast<float4*>(dst)     = make_float4(mg[0], mg[1], mg[2], mg[3]);
            *reinterpret_cast<float4*>(dst + 4) = make_float4(mg[4], mg[5], mg[6], mg[7]);
        }
    }
}

// ---------------- K2: e1 conv (k=3, pad=1), 129->128, relu ------------------
__global__ __launch_bounds__(128, 3) void k_e1(const float* __restrict__ w,
                                               const float* __restrict__ bias) {
    const int t  = blockIdx.z;
    const int c0 = blockIdx.y * 16;
    const int b  = (blockIdx.x * 128 + threadIdx.x) * 8;
    __shared__ float ws[129][3][16];          // 24.75 KB
    for (int idx = threadIdx.x; idx < 129 * 3 * 16; idx += 128) {
        int ic = idx / 48, r = idx % 48, j = r >> 4, cc = r & 15;
        ws[ic][j][cc] = w[((size_t)(c0 + cc) * 129 + ic) * 3 + j];
    }
    u64 acc[8][8];
    init_bias8(acc, bias, c0);
    __syncthreads();

    const bool hasL = (t >= 1), hasR = (t < 3);
    for (int ic = 0; ic < 129; ic++) {
        const size_t base = (size_t)(ic * 4 + t) * B_ + b;
        if (hasL) tap_row(ws[ic][0], &g_mag[base - B_], acc);
        tap_row(ws[ic][1], &g_mag[base], acc);
        if (hasR) tap_row(ws[ic][2], &g_mag[base + B_], acc);
    }
#pragma unroll
    for (int m = 0; m < 8; m++) {
        int c = c0 + 2 * m;
        store_pair(&g_out1[(size_t)(c * 4 + t) * B_ + b],
                   &g_out1[(size_t)((c + 1) * 4 + t) * B_ + b], acc[m], true);
    }
}

// ---------------- K3: e2 conv (k=3, pad=1, stride=2), 128->64, relu ---------
__global__ __launch_bounds__(128, 3) void k_e2(const float* __restrict__ w,
                                               const float* __restrict__ bias) {
    const int tp = blockIdx.z;
    const int c0 = blockIdx.y * 16;
    const int b  = (blockIdx.x * 128 + threadIdx.x) * 8;
    __shared__ float ws[128][3][16];          // 24 KB
    for (int idx = threadIdx.x; idx < 128 * 3 * 16; idx += 128) {
        int ic = idx / 48, r = idx % 48, j = r >> 4, cc = r & 15;
        ws[ic][j][cc] = w[((size_t)(c0 + cc) * 128 + ic) * 3 + j];
    }
    u64 acc[8][8];
    init_bias8(acc, bias, c0);
    __syncthreads();

    const int tt0 = 2 * tp - 1;
    const bool hasL = (tt0 >= 0);
    for (int ic = 0; ic < 128; ic++) {
        const size_t base = (size_t)(ic * 4 + tt0) * B_ + b;   // row tt0 (may be invalid if !hasL)
        if (hasL) tap_row(ws[ic][0], &g_out1[base], acc);
        tap_row(ws[ic][1], &g_out1[base + B_], acc);
        tap_row(ws[ic][2], &g_out1[base + 2u * B_], acc);
    }
#pragma unroll
    for (int m = 0; m < 8; m++) {
        int c = c0 + 2 * m;
        store_pair(&g_out2[(size_t)(c * 2 + tp) * B_ + b],
                   &g_out2[(size_t)((c + 1) * 2 + tp) * B_ + b], acc[m], true);
    }
}

// ---------------- generic GEMM core: K rows of src -> 16-channel tile -------
// manual next-row prefetch to keep LDG latency off the critical path.
template <int K>
__device__ __forceinline__ void gemm8(const float ws[][16], const float* src,
                                      int b, u64 (&acc)[8][8]) {
    float4 n0 = *reinterpret_cast<const float4*>(&src[b]);
    float4 n1 = *reinterpret_cast<const float4*>(&src[b + 4]);
    for (int k = 0; k < K; k++) {
        float4 c0 = n0, c1 = n1;
        if (k + 1 < K) {
            const float* p = &src[(size_t)(k + 1) * B_ + b];
            n0 = *reinterpret_cast<const float4*>(p);
            n1 = *reinterpret_cast<const float4*>(p + 4);
        }
        tap_v(ws[k], c0, c1, acc);
    }
}

// ---------------- K4: e3 (GEMM K=128 over g_out2), relu ---------------------
__global__ __launch_bounds__(128, 3) void k_e3(const float* __restrict__ w,
                                               const float* __restrict__ bias) {
    const int c0 = blockIdx.y * 16;
    const int b  = (blockIdx.x * 128 + threadIdx.x) * 8;
    __shared__ float ws[128][16];
    for (int idx = threadIdx.x; idx < 128 * 16; idx += 128) {
        int k = idx >> 4, cc = idx & 15, ic = k >> 1, tp = k & 1;
        ws[k][cc] = w[((size_t)(c0 + cc) * 64 + ic) * 3 + 1 + tp];
    }
    u64 acc[8][8];
    init_bias8(acc, bias, c0);
    __syncthreads();
    gemm8<128>(ws, g_out2, b, acc);
#pragma unroll
    for (int m = 0; m < 8; m++) {
        int c = c0 + 2 * m;
        store_pair(&g_out3[(size_t)c * B_ + b],
                   &g_out3[(size_t)(c + 1) * B_ + b], acc[m], true);
    }
}

// ---------------- K5: e4 (GEMM K=64 over g_out3, tap j=1), relu -------------
__global__ __launch_bounds__(128, 3) void k_e4(const float* __restrict__ w,
                                               const float* __restrict__ bias) {
    const int c0 = blockIdx.y * 16;
    const int b  = (blockIdx.x * 128 + threadIdx.x) * 8;
    __shared__ float ws[64][16];
    for (int idx = threadIdx.x; idx < 64 * 16; idx += 128) {
        int k = idx >> 4, cc = idx & 15;
        ws[k][cc] = w[((size_t)(c0 + cc) * 64 + k) * 3 + 1];
    }
    u64 acc[8][8];
    init_bias8(acc, bias, c0);
    __syncthreads();
    gemm8<64>(ws, g_out3, b, acc);
#pragma unroll
    for (int m = 0; m < 8; m++) {
        int c = c0 + 2 * m;
        store_pair(&g_out4[(size_t)c * B_ + b],
                   &g_out4[(size_t)(c + 1) * B_ + b], acc[m], true);
    }
}

// ---------------- K6: LSTM gates (GEMM K=128 over g_out4) -------------------
__global__ __launch_bounds__(128, 3) void k_gates(const float* __restrict__ w_ih,
                                                  const float* __restrict__ b_ih,
                                                  const float* __restrict__ b_hh) {
    const int g0 = blockIdx.y * 16;
    const int b  = (blockIdx.x * 128 + threadIdx.x) * 8;
    __shared__ float ws[128][16];
    for (int idx = threadIdx.x; idx < 128 * 16; idx += 128) {
        int k = idx >> 4, cc = idx & 15;
        ws[k][cc] = w_ih[(size_t)(g0 + cc) * 128 + k];
    }
    u64 acc[8][8];
#pragma unroll
    for (int m = 0; m < 8; m++) {
        u64 bv = pack2(b_ih[g0 + 2 * m] + b_hh[g0 + 2 * m],
                       b_ih[g0 + 2 * m + 1] + b_hh[g0 + 2 * m + 1]);
#pragma unroll
        for (int p = 0; p < 8; p++) acc[m][p] = bv;
    }
    __syncthreads();
    gemm8<128>(ws, g_out4, b, acc);
#pragma unroll
    for (int m = 0; m < 8; m++) {
        int g = g0 + 2 * m;
        store_pair(&g_gates[(size_t)g * B_ + b],
                   &g_gates[(size_t)(g + 1) * B_ + b], acc[m], false);
    }
}

// ---------------- K7: LSTM pointwise (h0=c0=0) + decoder + sigmoid ----------
__device__ __forceinline__ float sigf(float x) { return 1.f / (1.f + expf(-x)); }

__global__ __launch_bounds__(256) void k_head(const float* __restrict__ dec_w,
                                              const float* __restrict__ dec_b,
                                              float* __restrict__ out) {
    const int b = (blockIdx.x * 256 + threadIdx.x) * 2;
    __shared__ float wd[128];
    if (threadIdx.x < 128) wd[threadIdx.x] = dec_w[threadIdx.x];
    __syncthreads();
    float d0 = dec_b[0], d1 = d0;
    for (int c = 0; c < 128; c++) {
        u64 ig = ld2(&g_gates[(size_t)(      c) * B_ + b]);
        u64 gg = ld2(&g_gates[(size_t)(256 + c) * B_ + b]);
        u64 og = ld2(&g_gates[(size_t)(384 + c) * B_ + b]);
        float wc = wd[c];
        float cA = sigf(lo32(ig)) * tanhf(lo32(gg));
        float hA = sigf(lo32(og)) * tanhf(cA);
        d0 += fmaxf(hA, 0.f) * wc;
        float cB = sigf(hi32(ig)) * tanhf(hi32(gg));
        float hB = sigf(hi32(og)) * tanhf(cB);
        d1 += fmaxf(hB, 0.f) * wc;
    }
    st2(&out[b], pack2(sigf(d0), sigf(d1)));
}

// ---------------- launch -----------------------------------------------------
extern "C" void kernel_launch(void* const* d_in, const int* in_sizes, int n_in,
                              void* d_out, int out_size) {
    const float* data   = (const float*)d_in[0];
    // d_in[1] = sr (16000 -> context 64, baked in)
    const float* stft_w = (const float*)d_in[2];
    const float* e1_w   = (const float*)d_in[3];
    const float* e1_b   = (const float*)d_in[4];
    const float* e2_w   = (const float*)d_in[5];
    const float* e2_b   = (const float*)d_in[6];
    const float* e3_w   = (const float*)d_in[7];
    const float* e3_b   = (const float*)d_in[8];
    const float* e4_w   = (const float*)d_in[9];
    const float* e4_b   = (const float*)d_in[10];
    const float* w_ih   = (const float*)d_in[11];
    // d_in[12] = w_hh (dead: h0 == 0)
    const float* b_ih   = (const float*)d_in[13];
    const float* b_hh   = (const float*)d_in[14];
    const float* dec_w  = (const float*)d_in[15];
    const float* dec_b  = (const float*)d_in[16];
    float* out = (float*)d_out;

    dim3 blk(128);
    const int GX = B_ / 1024;                 // 64 blocks over batch (8/thread, 128 thr)
    k_transpose<<<dim3(B_ / 32, 16), dim3(32, 8)>>>(data);
    k_stft     <<<dim3(GX, 17, 4), blk>>>(stft_w);   // 17*8 >= 129 freqs
    k_e1       <<<dim3(GX, 8, 4),  blk>>>(e1_w, e1_b);
    k_e2       <<<dim3(GX, 4, 2),  blk>>>(e2_w, e2_b);
    k_e3       <<<dim3(GX, 4),     blk>>>(e3_w, e3_b);
    k_e4       <<<dim3(GX, 8),     blk>>>(e4_w, e4_b);
    k_gates    <<<dim3(GX, 32),    blk>>>(w_ih, b_ih, b_hh);
    k_head     <<<dim3(B_ / 512),  dim3(256)>>>(dec_w, dec_b, out);
}

// round 13
// speedup vs baseline: 1.8056x; 1.8056x over previous
#include <cuda_runtime.h>
#include <math.h>

#define B_ 65536
typedef unsigned long long u64;
typedef ulonglong2 u64x2;

// ---------------- f32x2 helpers (FFMA2 only reachable via PTX) --------------
__device__ __forceinline__ u64 fma2(u64 w, u64 a, u64 c) {
    u64 d; asm("fma.rn.f32x2 %0, %1, %2, %3;" : "=l"(d) : "l"(w), "l"(a), "l"(c));
    return d;
}
__device__ __forceinline__ u64 pack2(float x, float y) {
    u64 d; asm("mov.b64 %0, {%1, %2};" : "=l"(d)
               : "r"(__float_as_uint(x)), "r"(__float_as_uint(y)));
    return d;
}
__device__ __forceinline__ float lo32(u64 v) { return __uint_as_float((unsigned)v); }
__device__ __forceinline__ float hi32(u64 v) { return __uint_as_float((unsigned)(v >> 32)); }
__device__ __forceinline__ u64 ld2(const float* p) { return *reinterpret_cast<const u64*>(p); }
__device__ __forceinline__ void st2(float* p, u64 v) { *reinterpret_cast<u64*>(p) = v; }

__device__ __forceinline__ float4 relu4(float4 v) {
    return make_float4(fmaxf(v.x, 0.f), fmaxf(v.y, 0.f),
                       fmaxf(v.z, 0.f), fmaxf(v.w, 0.f));
}

// ---------------- scratch (device globals; no allocations) ------------------
__device__ float g_dataT[512u * B_];   // [s][b]
__device__ float g_mag  [516u * B_];   // [(f*4+t)][b]   f<129, t<4
__device__ float g_out1 [512u * B_];   // [(c*4+t)][b]   c<128
__device__ float g_out2 [128u * B_];   // [(c*2+t)][b]   c<64
__device__ float g_out3 [ 64u * B_];   // [c][b]
__device__ float g_out4 [128u * B_];   // [c][b]
__device__ float g_gates[512u * B_];   // [g][b]

// ---- core tap: 16 floats of weights (warp-uniform, SMEM) x 4 batches -------
// acc[m][p]: f32x2 = output channels (c0+2m, c0+2m+1), batch b+p.
__device__ __forceinline__ void tap16(const float* __restrict__ wrow,
                                      float4 v, u64 (&acc)[8][4]) {
    u64 A0 = pack2(v.x, v.x), A1 = pack2(v.y, v.y),
        A2 = pack2(v.z, v.z), A3 = pack2(v.w, v.w);
#pragma unroll
    for (int q = 0; q < 4; q++) {
        u64x2 W = *reinterpret_cast<const u64x2*>(wrow + 4 * q);
        acc[2*q  ][0] = fma2(W.x, A0, acc[2*q  ][0]);
        acc[2*q  ][1] = fma2(W.x, A1, acc[2*q  ][1]);
        acc[2*q  ][2] = fma2(W.x, A2, acc[2*q  ][2]);
        acc[2*q  ][3] = fma2(W.x, A3, acc[2*q  ][3]);
        acc[2*q+1][0] = fma2(W.y, A0, acc[2*q+1][0]);
        acc[2*q+1][1] = fma2(W.y, A1, acc[2*q+1][1]);
        acc[2*q+1][2] = fma2(W.y, A2, acc[2*q+1][2]);
        acc[2*q+1][3] = fma2(W.y, A3, acc[2*q+1][3]);
    }
}
__device__ __forceinline__ float4 lo4(const u64 a[4]) {
    return make_float4(lo32(a[0]), lo32(a[1]), lo32(a[2]), lo32(a[3]));
}
__device__ __forceinline__ float4 hi4(const u64 a[4]) {
    return make_float4(hi32(a[0]), hi32(a[1]), hi32(a[2]), hi32(a[3]));
}
__device__ __forceinline__ void init_bias(u64 (&acc)[8][4],
                                          const float* bias, int c0) {
#pragma unroll
    for (int m = 0; m < 8; m++) {
        u64 bv = pack2(bias[c0 + 2 * m], bias[c0 + 2 * m + 1]);
#pragma unroll
        for (int p = 0; p < 4; p++) acc[m][p] = bv;
    }
}

// ---------------- K0: transpose data[B][512] -> dataT[512][B] ---------------
__global__ void k_transpose(const float* __restrict__ x) {
    __shared__ float tile[32][33];
    int b0 = blockIdx.x * 32, s0 = blockIdx.y * 32;
    int tx = threadIdx.x, ty = threadIdx.y;   // 32 x 8
#pragma unroll
    for (int i = 0; i < 32; i += 8)
        tile[ty + i][tx] = x[(size_t)(b0 + ty + i) * 512 + s0 + tx];
    __syncthreads();
#pragma unroll
    for (int i = 0; i < 32; i += 8)
        g_dataT[(size_t)(s0 + ty + i) * B_ + b0 + tx] = tile[tx][ty + i];
}

// ---------------- K1: STFT (stride 128) fused with mag ----------------------
// f32x2 lanes = (Real_f, Imag_f); 8 freqs/tile, 4 batches/thread.
//   t<3        : s = 128*t - 64 + kk  (kk < 64-128t -> contribution is zero, skipped)
//   t=3, kk<192: s = 320 + kk ; kk>=192: s = 702 - kk (reflect)
__global__ __launch_bounds__(256, 2) void k_stft(const float* __restrict__ w) {
    const int t  = blockIdx.z;
    const int f0 = blockIdx.y * 8;
    const int b  = (blockIdx.x * 256 + threadIdx.x) * 4;
    __shared__ float ws[256][16];             // [kk][2*m + isImag]
    for (int idx = threadIdx.x; idx < 256 * 16; idx += 256) {
        int kk = idx >> 4, r = idx & 15, m = r >> 1, isI = r & 1;
        int f = f0 + m;
        ws[kk][r] = (f < 129) ? w[(f + 129 * isI) * 256 + kk] : 0.f;
    }
    u64 acc[8][4];
#pragma unroll
    for (int m = 0; m < 8; m++)
#pragma unroll
        for (int p = 0; p < 4; p++) acc[m][p] = 0ull;
    __syncthreads();

    const int kk0 = (t == 0) ? 64 : 0;        // zero-context region: skip
#pragma unroll 4
    for (int kk = kk0; kk < 256; kk++) {
        int s = (t < 3) ? (128 * t - 64 + kk)
                        : ((kk < 192) ? (320 + kk) : (702 - kk));
        float4 v = *reinterpret_cast<const float4*>(&g_dataT[(size_t)s * B_ + b]);
        tap16(ws[kk], v, acc);
    }
#pragma unroll
    for (int m = 0; m < 8; m++) {
        int f = f0 + m;
        if (f < 129) {
            float4 mg;
            mg.x = sqrtf(lo32(acc[m][0]) * lo32(acc[m][0]) + hi32(acc[m][0]) * hi32(acc[m][0]));
            mg.y = sqrtf(lo32(acc[m][1]) * lo32(acc[m][1]) + hi32(acc[m][1]) * hi32(acc[m][1]));
            mg.z = sqrtf(lo32(acc[m][2]) * lo32(acc[m][2]) + hi32(acc[m][2]) * hi32(acc[m][2]));
            mg.w = sqrtf(lo32(acc[m][3]) * lo32(acc[m][3]) + hi32(acc[m][3]) * hi32(acc[m][3]));
            *reinterpret_cast<float4*>(&g_mag[(size_t)(f * 4 + t) * B_ + b]) = mg;
        }
    }
}

// ---------------- K2: e1 conv (k=3, pad=1), 129->128, relu ------------------
__global__ __launch_bounds__(256, 2) void k_e1(const float* __restrict__ w,
                                               const float* __restrict__ bias) {
    const int t  = blockIdx.z;
    const int c0 = blockIdx.y * 16;
    const int b  = (blockIdx.x * 256 + threadIdx.x) * 4;
    __shared__ float ws[129][3][16];          // 24.75 KB
    for (int idx = threadIdx.x; idx < 129 * 3 * 16; idx += 256) {
        int ic = idx / 48, r = idx % 48, j = r >> 4, cc = r & 15;
        ws[ic][j][cc] = w[((size_t)(c0 + cc) * 129 + ic) * 3 + j];
    }
    u64 acc[8][4];
    init_bias(acc, bias, c0);
    __syncthreads();

    const bool hasL = (t >= 1), hasR = (t < 3);
    for (int ic = 0; ic < 129; ic++) {
        const size_t base = (size_t)(ic * 4 + t) * B_ + b;
        if (hasL) {
            float4 v0 = *reinterpret_cast<const float4*>(&g_mag[base - B_]);
            tap16(ws[ic][0], v0, acc);
        }
        {
            float4 v1 = *reinterpret_cast<const float4*>(&g_mag[base]);
            tap16(ws[ic][1], v1, acc);
        }
        if (hasR) {
            float4 v2 = *reinterpret_cast<const float4*>(&g_mag[base + B_]);
            tap16(ws[ic][2], v2, acc);
        }
    }
#pragma unroll
    for (int m = 0; m < 8; m++) {
        int c = c0 + 2 * m;
        *reinterpret_cast<float4*>(&g_out1[(size_t)(c * 4 + t) * B_ + b])       = relu4(lo4(acc[m]));
        *reinterpret_cast<float4*>(&g_out1[(size_t)((c + 1) * 4 + t) * B_ + b]) = relu4(hi4(acc[m]));
    }
}

// ---------------- K3: e2 conv (k=3, pad=1, stride=2), 128->64, relu ---------
__global__ __launch_bounds__(256, 2) void k_e2(const float* __restrict__ w,
                                               const float* __restrict__ bias) {
    const int tp = blockIdx.z;
    const int c0 = blockIdx.y * 16;
    const int b  = (blockIdx.x * 256 + threadIdx.x) * 4;
    __shared__ float ws[128][3][16];          // 24 KB
    for (int idx = threadIdx.x; idx < 128 * 3 * 16; idx += 256) {
        int ic = idx / 48, r = idx % 48, j = r >> 4, cc = r & 15;
        ws[ic][j][cc] = w[((size_t)(c0 + cc) * 128 + ic) * 3 + j];
    }
    u64 acc[8][4];
    init_bias(acc, bias, c0);
    __syncthreads();

    const int tt0 = 2 * tp - 1;
    const bool hasL = (tt0 >= 0);             // tp=0 left tap is zero padding
    for (int ic = 0; ic < 128; ic++) {
        const size_t row0 = (size_t)(ic * 4) * B_ + b;
        if (hasL) {
            float4 v0 = *reinterpret_cast<const float4*>(&g_out1[row0 + (size_t)tt0 * B_]);
            tap16(ws[ic][0], v0, acc);
        }
        {
            float4 v1 = *reinterpret_cast<const float4*>(&g_out1[row0 + (size_t)(tt0 + 1) * B_]);
            tap16(ws[ic][1], v1, acc);
        }
        {
            float4 v2 = *reinterpret_cast<const float4*>(&g_out1[row0 + (size_t)(tt0 + 2) * B_]);
            tap16(ws[ic][2], v2, acc);
        }
    }
#pragma unroll
    for (int m = 0; m < 8; m++) {
        int c = c0 + 2 * m;
        *reinterpret_cast<float4*>(&g_out2[(size_t)(c * 2 + tp) * B_ + b])       = relu4(lo4(acc[m]));
        *reinterpret_cast<float4*>(&g_out2[(size_t)((c + 1) * 2 + tp) * B_ + b]) = relu4(hi4(acc[m]));
    }
}

// ---------------- generic GEMM core: K rows of src -> 16-channel tile -------
template <int K>
__device__ __forceinline__ void gemm_core(const float ws[][16], const float* src,
                                          int b, u64 (&acc)[8][4]) {
#pragma unroll 4
    for (int k = 0; k < K; k++) {
        float4 v = *reinterpret_cast<const float4*>(&src[(size_t)k * B_ + b]);
        tap16(ws[k], v, acc);
    }
}

// ---------------- K4: e3 (GEMM K=128 over g_out2), relu ---------------------
__global__ __launch_bounds__(256, 2) void k_e3(const float* __restrict__ w,
                                               const float* __restrict__ bias) {
    const int c0 = blockIdx.y * 16;
    const int b  = (blockIdx.x * 256 + threadIdx.x) * 4;
    __shared__ float ws[128][16];
    for (int idx = threadIdx.x; idx < 128 * 16; idx += 256) {
        int k = idx >> 4, cc = idx & 15, ic = k >> 1, tp = k & 1;
        ws[k][cc] = w[((size_t)(c0 + cc) * 64 + ic) * 3 + 1 + tp];
    }
    u64 acc[8][4];
    init_bias(acc, bias, c0);
    __syncthreads();
    gemm_core<128>(ws, g_out2, b, acc);
#pragma unroll
    for (int m = 0; m < 8; m++) {
        int c = c0 + 2 * m;
        *reinterpret_cast<float4*>(&g_out3[(size_t)c * B_ + b])       = relu4(lo4(acc[m]));
        *reinterpret_cast<float4*>(&g_out3[(size_t)(c + 1) * B_ + b]) = relu4(hi4(acc[m]));
    }
}

// ---------------- K5: e4 (GEMM K=64 over g_out3, tap j=1), relu -------------
__global__ __launch_bounds__(256, 2) void k_e4(const float* __restrict__ w,
                                               const float* __restrict__ bias) {
    const int c0 = blockIdx.y * 16;
    const int b  = (blockIdx.x * 256 + threadIdx.x) * 4;
    __shared__ float ws[64][16];
    for (int idx = threadIdx.x; idx < 64 * 16; idx += 256) {
        int k = idx >> 4, cc = idx & 15;
        ws[k][cc] = w[((size_t)(c0 + cc) * 64 + k) * 3 + 1];
    }
    u64 acc[8][4];
    init_bias(acc, bias, c0);
    __syncthreads();
    gemm_core<64>(ws, g_out3, b, acc);
#pragma unroll
    for (int m = 0; m < 8; m++) {
        int c = c0 + 2 * m;
        *reinterpret_cast<float4*>(&g_out4[(size_t)c * B_ + b])       = relu4(lo4(acc[m]));
        *reinterpret_cast<float4*>(&g_out4[(size_t)(c + 1) * B_ + b]) = relu4(hi4(acc[m]));
    }
}

// ---------------- K6: LSTM gates (GEMM K=128 over g_out4) -------------------
__global__ __launch_bounds__(256, 2) void k_gates(const float* __restrict__ w_ih,
                                                  const float* __restrict__ b_ih,
                                                  const float* __restrict__ b_hh) {
    const int g0 = blockIdx.y * 16;
    const int b  = (blockIdx.x * 256 + threadIdx.x) * 4;
    __shared__ float ws[128][16];
    for (int idx = threadIdx.x; idx < 128 * 16; idx += 256) {
        int k = idx >> 4, cc = idx & 15;
        ws[k][cc] = w_ih[(size_t)(g0 + cc) * 128 + k];
    }
    u64 acc[8][4];
#pragma unroll
    for (int m = 0; m < 8; m++) {
        u64 bv = pack2(b_ih[g0 + 2 * m] + b_hh[g0 + 2 * m],
                       b_ih[g0 + 2 * m + 1] + b_hh[g0 + 2 * m + 1]);
#pragma unroll
        for (int p = 0; p < 4; p++) acc[m][p] = bv;
    }
    __syncthreads();
    gemm_core<128>(ws, g_out4, b, acc);
#pragma unroll
    for (int m = 0; m < 8; m++) {
        int g = g0 + 2 * m;
        *reinterpret_cast<float4*>(&g_gates[(size_t)g * B_ + b])       = lo4(acc[m]);
        *reinterpret_cast<float4*>(&g_gates[(size_t)(g + 1) * B_ + b]) = hi4(acc[m]);
    }
}

// ---------------- K7: LSTM pointwise (h0=c0=0) + decoder + sigmoid ----------
__device__ __forceinline__ float sigf(float x) { return 1.f / (1.f + expf(-x)); }

__global__ __launch_bounds__(256) void k_head(const float* __restrict__ dec_w,
                                              const float* __restrict__ dec_b,
                                              float* __restrict__ out) {
    const int b = (blockIdx.x * 256 + threadIdx.x) * 2;
    __shared__ float wd[128];
    if (threadIdx.x < 128) wd[threadIdx.x] = dec_w[threadIdx.x];
    __syncthreads();
    float d0 = dec_b[0], d1 = d0;
    for (int c = 0; c < 128; c++) {
        u64 ig = ld2(&g_gates[(size_t)(      c) * B_ + b]);
        u64 gg = ld2(&g_gates[(size_t)(256 + c) * B_ + b]);
        u64 og = ld2(&g_gates[(size_t)(384 + c) * B_ + b]);
        float wc = wd[c];
        float cA = sigf(lo32(ig)) * tanhf(lo32(gg));
        float hA = sigf(lo32(og)) * tanhf(cA);
        d0 += fmaxf(hA, 0.f) * wc;
        float cB = sigf(hi32(ig)) * tanhf(hi32(gg));
        float hB = sigf(hi32(og)) * tanhf(cB);
        d1 += fmaxf(hB, 0.f) * wc;
    }
    st2(&out[b], pack2(sigf(d0), sigf(d1)));
}

// ---------------- launch -----------------------------------------------------
extern "C" void kernel_launch(void* const* d_in, const int* in_sizes, int n_in,
                              void* d_out, int out_size) {
    const float* data   = (const float*)d_in[0];
    // d_in[1] = sr (16000 -> context 64, baked in)
    const float* stft_w = (const float*)d_in[2];
    const float* e1_w   = (const float*)d_in[3];
    const float* e1_b   = (const float*)d_in[4];
    const float* e2_w   = (const float*)d_in[5];
    const float* e2_b   = (const float*)d_in[6];
    const float* e3_w   = (const float*)d_in[7];
    const float* e3_b   = (const float*)d_in[8];
    const float* e4_w   = (const float*)d_in[9];
    const float* e4_b   = (const float*)d_in[10];
    const float* w_ih   = (const float*)d_in[11];
    // d_in[12] = w_hh (dead: h0 == 0)
    const float* b_ih   = (const float*)d_in[13];
    const float* b_hh   = (const float*)d_in[14];
    const float* dec_w  = (const float*)d_in[15];
    const float* dec_b  = (const float*)d_in[16];
    float* out = (float*)d_out;

    dim3 blk(256);
    const int GX = B_ / 1024;                 // 64 blocks over batch (4/thread)
    k_transpose<<<dim3(B_ / 32, 16), dim3(32, 8)>>>(data);
    k_stft     <<<dim3(GX, 17, 4), blk>>>(stft_w);   // 17*8 >= 129 freqs
    k_e1       <<<dim3(GX, 8, 4),  blk>>>(e1_w, e1_b);
    k_e2       <<<dim3(GX, 4, 2),  blk>>>(e2_w, e2_b);
    k_e3       <<<dim3(GX, 4),     blk>>>(e3_w, e3_b);
    k_e4       <<<dim3(GX, 8),     blk>>>(e4_w, e4_b);
    k_gates    <<<dim3(GX, 32),    blk>>>(w_ih, b_ih, b_hh);
    k_head     <<<dim3(B_ / 512),  dim3(256)>>>(dec_w, dec_b, out);
}

// round 17
// speedup vs baseline: 2.4090x; 1.3342x over previous
#include <cuda_runtime.h>
#include <math.h>

#define B_ 65536
typedef unsigned long long u64;
typedef ulonglong2 u64x2;

// ---------------- f32x2 helpers (FFMA2 only reachable via PTX) --------------
__device__ __forceinline__ u64 fma2(u64 w, u64 a, u64 c) {
    u64 d; asm("fma.rn.f32x2 %0, %1, %2, %3;" : "=l"(d) : "l"(w), "l"(a), "l"(c));
    return d;
}
__device__ __forceinline__ u64 pack2(float x, float y) {
    u64 d; asm("mov.b64 %0, {%1, %2};" : "=l"(d)
               : "r"(__float_as_uint(x)), "r"(__float_as_uint(y)));
    return d;
}
__device__ __forceinline__ float lo32(u64 v) { return __uint_as_float((unsigned)v); }
__device__ __forceinline__ float hi32(u64 v) { return __uint_as_float((unsigned)(v >> 32)); }
__device__ __forceinline__ u64 ld2(const float* p) { return *reinterpret_cast<const u64*>(p); }
__device__ __forceinline__ void st2(float* p, u64 v) { *reinterpret_cast<u64*>(p) = v; }

__device__ __forceinline__ float4 relu4(float4 v) {
    return make_float4(fmaxf(v.x, 0.f), fmaxf(v.y, 0.f),
                       fmaxf(v.z, 0.f), fmaxf(v.w, 0.f));
}

// ---------------- scratch (device globals; no allocations) ------------------
__device__ float g_dataT[512u * B_];   // [s][b]
__device__ float g_mag  [516u * B_];   // [(f*4+t)][b]   f<129, t<4
__device__ float g_out1 [512u * B_];   // [(c*4+t)][b]   c<128
__device__ float g_out2 [128u * B_];   // [(c*2+t)][b]   c<64
__device__ float g_out3 [ 64u * B_];   // [c][b]
__device__ float g_out4 [128u * B_];   // [c][b]
__device__ float g_gates[512u * B_];   // [g][b]

// ---- core tap: 16 floats of weights (warp-uniform, SMEM) x 4 batches -------
// acc[m][p]: f32x2 = output channels (c0+2m, c0+2m+1), batch b+p.
__device__ __forceinline__ void tap16(const float* __restrict__ wrow,
                                      float4 v, u64 (&acc)[8][4]) {
    u64 A0 = pack2(v.x, v.x), A1 = pack2(v.y, v.y),
        A2 = pack2(v.z, v.z), A3 = pack2(v.w, v.w);
#pragma unroll
    for (int q = 0; q < 4; q++) {
        u64x2 W = *reinterpret_cast<const u64x2*>(wrow + 4 * q);
        acc[2*q  ][0] = fma2(W.x, A0, acc[2*q  ][0]);
        acc[2*q  ][1] = fma2(W.x, A1, acc[2*q  ][1]);
        acc[2*q  ][2] = fma2(W.x, A2, acc[2*q  ][2]);
        acc[2*q  ][3] = fma2(W.x, A3, acc[2*q  ][3]);
        acc[2*q+1][0] = fma2(W.y, A0, acc[2*q+1][0]);
        acc[2*q+1][1] = fma2(W.y, A1, acc[2*q+1][1]);
        acc[2*q+1][2] = fma2(W.y, A2, acc[2*q+1][2]);
        acc[2*q+1][3] = fma2(W.y, A3, acc[2*q+1][3]);
    }
}
__device__ __forceinline__ float4 lo4(const u64 a[4]) {
    return make_float4(lo32(a[0]), lo32(a[1]), lo32(a[2]), lo32(a[3]));
}
__device__ __forceinline__ float4 hi4(const u64 a[4]) {
    return make_float4(hi32(a[0]), hi32(a[1]), hi32(a[2]), hi32(a[3]));
}
__device__ __forceinline__ void init_bias(u64 (&acc)[8][4],
                                          const float* bias, int c0) {
#pragma unroll
    for (int m = 0; m < 8; m++) {
        u64 bv = pack2(bias[c0 + 2 * m], bias[c0 + 2 * m + 1]);
#pragma unroll
        for (int p = 0; p < 4; p++) acc[m][p] = bv;
    }
}

// ---------------- K0: transpose data[B][512] -> dataT[512][B] ---------------
__global__ void k_transpose(const float* __restrict__ x) {
    __shared__ float tile[32][33];
    int b0 = blockIdx.x * 32, s0 = blockIdx.y * 32;
    int tx = threadIdx.x, ty = threadIdx.y;   // 32 x 8
#pragma unroll
    for (int i = 0; i < 32; i += 8)
        tile[ty + i][tx] = x[(size_t)(b0 + ty + i) * 512 + s0 + tx];
    __syncthreads();
#pragma unroll
    for (int i = 0; i < 32; i += 8)
        g_dataT[(size_t)(s0 + ty + i) * B_ + b0 + tx] = tile[tx][ty + i];
}

// ---------------- K1: STFT (stride 128) fused with mag ----------------------
// f32x2 lanes = (Real_f, Imag_f); 8 freqs/tile, 4 batches/thread.
//   t<3        : s = 128*t - 64 + kk  (kk < 64-128t -> zero contribution, skipped)
//   t=3, kk<192: s = 320 + kk ; kk>=192: s = 702 - kk (reflect)
__global__ __launch_bounds__(256, 2) void k_stft(const float* __restrict__ w) {
    const int t  = blockIdx.z;
    const int f0 = blockIdx.y * 8;
    const int b  = (blockIdx.x * 256 + threadIdx.x) * 4;
    __shared__ float ws[256][16];             // [kk][2*m + isImag]
    for (int idx = threadIdx.x; idx < 256 * 16; idx += 256) {
        int kk = idx >> 4, r = idx & 15, m = r >> 1, isI = r & 1;
        int f = f0 + m;
        ws[kk][r] = (f < 129) ? w[(f + 129 * isI) * 256 + kk] : 0.f;
    }
    u64 acc[8][4];
#pragma unroll
    for (int m = 0; m < 8; m++)
#pragma unroll
        for (int p = 0; p < 4; p++) acc[m][p] = 0ull;
    __syncthreads();

    const int kk0 = (t == 0) ? 64 : 0;        // zero-context region: skip
#pragma unroll 4
    for (int kk = kk0; kk < 256; kk++) {
        int s = (t < 3) ? (128 * t - 64 + kk)
                        : ((kk < 192) ? (320 + kk) : (702 - kk));
        float4 v = *reinterpret_cast<const float4*>(&g_dataT[(size_t)s * B_ + b]);
        tap16(ws[kk], v, acc);
    }
#pragma unroll
    for (int m = 0; m < 8; m++) {
        int f = f0 + m;
        if (f < 129) {
            float4 mg;
            mg.x = sqrtf(lo32(acc[m][0]) * lo32(acc[m][0]) + hi32(acc[m][0]) * hi32(acc[m][0]));
            mg.y = sqrtf(lo32(acc[m][1]) * lo32(acc[m][1]) + hi32(acc[m][1]) * hi32(acc[m][1]));
            mg.z = sqrtf(lo32(acc[m][2]) * lo32(acc[m][2]) + hi32(acc[m][2]) * hi32(acc[m][2]));
            mg.w = sqrtf(lo32(acc[m][3]) * lo32(acc[m][3]) + hi32(acc[m][3]) * hi32(acc[m][3]));
            *reinterpret_cast<float4*>(&g_mag[(size_t)(f * 4 + t) * B_ + b]) = mg;
        }
    }
}

// ---------------- K2: e1 conv (k=3, pad=1), 129->128, relu ------------------
// Boundary branch hoisted OUT of the ic loop; every body batches its loads
// (all LDGs issued before any tap) to keep MLP up.
__global__ __launch_bounds__(256, 2) void k_e1(const float* __restrict__ w,
                                               const float* __restrict__ bias) {
    const int t  = blockIdx.z;
    const int c0 = blockIdx.y * 16;
    const int b  = (blockIdx.x * 256 + threadIdx.x) * 4;
    __shared__ float ws[129][3][16];          // 24.75 KB
    for (int idx = threadIdx.x; idx < 129 * 3 * 16; idx += 256) {
        int ic = idx / 48, r = idx % 48, j = r >> 4, cc = r & 15;
        ws[ic][j][cc] = w[((size_t)(c0 + cc) * 129 + ic) * 3 + j];
    }
    u64 acc[8][4];
    init_bias(acc, bias, c0);
    __syncthreads();

    if (t == 0) {                             // taps {mid, right}
        for (int ic = 0; ic < 129; ic++) {
            const size_t base = (size_t)(ic * 4) * B_ + b;
            float4 v1 = *reinterpret_cast<const float4*>(&g_mag[base]);
            float4 v2 = *reinterpret_cast<const float4*>(&g_mag[base + B_]);
            tap16(ws[ic][1], v1, acc);
            tap16(ws[ic][2], v2, acc);
        }
    } else if (t == 3) {                      // taps {left, mid}
        for (int ic = 0; ic < 129; ic++) {
            const size_t base = (size_t)(ic * 4 + 3) * B_ + b;
            float4 v0 = *reinterpret_cast<const float4*>(&g_mag[base - B_]);
            float4 v1 = *reinterpret_cast<const float4*>(&g_mag[base]);
            tap16(ws[ic][0], v0, acc);
            tap16(ws[ic][1], v1, acc);
        }
    } else {                                  // full 3 taps
        for (int ic = 0; ic < 129; ic++) {
            const size_t base = (size_t)(ic * 4 + t) * B_ + b;
            float4 v0 = *reinterpret_cast<const float4*>(&g_mag[base - B_]);
            float4 v1 = *reinterpret_cast<const float4*>(&g_mag[base]);
            float4 v2 = *reinterpret_cast<const float4*>(&g_mag[base + B_]);
            tap16(ws[ic][0], v0, acc);
            tap16(ws[ic][1], v1, acc);
            tap16(ws[ic][2], v2, acc);
        }
    }
#pragma unroll
    for (int m = 0; m < 8; m++) {
        int c = c0 + 2 * m;
        *reinterpret_cast<float4*>(&g_out1[(size_t)(c * 4 + t) * B_ + b])       = relu4(lo4(acc[m]));
        *reinterpret_cast<float4*>(&g_out1[(size_t)((c + 1) * 4 + t) * B_ + b]) = relu4(hi4(acc[m]));
    }
}

// ---------------- K3: e2 conv (k=3, pad=1, stride=2), 128->64, relu ---------
__global__ __launch_bounds__(256, 2) void k_e2(const float* __restrict__ w,
                                               const float* __restrict__ bias) {
    const int tp = blockIdx.z;
    const int c0 = blockIdx.y * 16;
    const int b  = (blockIdx.x * 256 + threadIdx.x) * 4;
    __shared__ float ws[128][3][16];          // 24 KB
    for (int idx = threadIdx.x; idx < 128 * 3 * 16; idx += 256) {
        int ic = idx / 48, r = idx % 48, j = r >> 4, cc = r & 15;
        ws[ic][j][cc] = w[((size_t)(c0 + cc) * 128 + ic) * 3 + j];
    }
    u64 acc[8][4];
    init_bias(acc, bias, c0);
    __syncthreads();

    if (tp == 0) {                            // tt = {0, 1}: taps {mid, right}
        for (int ic = 0; ic < 128; ic++) {
            const size_t base = (size_t)(ic * 4) * B_ + b;
            float4 v1 = *reinterpret_cast<const float4*>(&g_out1[base]);
            float4 v2 = *reinterpret_cast<const float4*>(&g_out1[base + B_]);
            tap16(ws[ic][1], v1, acc);
            tap16(ws[ic][2], v2, acc);
        }
    } else {                                  // tt = {1, 2, 3}: all taps
        for (int ic = 0; ic < 128; ic++) {
            const size_t base = (size_t)(ic * 4 + 1) * B_ + b;
            float4 v0 = *reinterpret_cast<const float4*>(&g_out1[base]);
            float4 v1 = *reinterpret_cast<const float4*>(&g_out1[base + B_]);
            float4 v2 = *reinterpret_cast<const float4*>(&g_out1[base + 2u * B_]);
            tap16(ws[ic][0], v0, acc);
            tap16(ws[ic][1], v1, acc);
            tap16(ws[ic][2], v2, acc);
        }
    }
#pragma unroll
    for (int m = 0; m < 8; m++) {
        int c = c0 + 2 * m;
        *reinterpret_cast<float4*>(&g_out2[(size_t)(c * 2 + tp) * B_ + b])       = relu4(lo4(acc[m]));
        *reinterpret_cast<float4*>(&g_out2[(size_t)((c + 1) * 2 + tp) * B_ + b]) = relu4(hi4(acc[m]));
    }
}

// ---------------- generic GEMM core: K rows of src -> 16-channel tile -------
template <int K>
__device__ __forceinline__ void gemm_core(const float ws[][16], const float* src,
                                          int b, u64 (&acc)[8][4]) {
#pragma unroll 4
    for (int k = 0; k < K; k++) {
        float4 v = *reinterpret_cast<const float4*>(&src[(size_t)k * B_ + b]);
        tap16(ws[k], v, acc);
    }
}

// ---------------- K4: e3 (GEMM K=128 over g_out2), relu ---------------------
__global__ __launch_bounds__(256, 2) void k_e3(const float* __restrict__ w,
                                               const float* __restrict__ bias) {
    const int c0 = blockIdx.y * 16;
    const int b  = (blockIdx.x * 256 + threadIdx.x) * 4;
    __shared__ float ws[128][16];
    for (int idx = threadIdx.x; idx < 128 * 16; idx += 256) {
        int k = idx >> 4, cc = idx & 15, ic = k >> 1, tp = k & 1;
        ws[k][cc] = w[((size_t)(c0 + cc) * 64 + ic) * 3 + 1 + tp];
    }
    u64 acc[8][4];
    init_bias(acc, bias, c0);
    __syncthreads();
    gemm_core<128>(ws, g_out2, b, acc);
#pragma unroll
    for (int m = 0; m < 8; m++) {
        int c = c0 + 2 * m;
        *reinterpret_cast<float4*>(&g_out3[(size_t)c * B_ + b])       = relu4(lo4(acc[m]));
        *reinterpret_cast<float4*>(&g_out3[(size_t)(c + 1) * B_ + b]) = relu4(hi4(acc[m]));
    }
}

// ---------------- K5: e4 (GEMM K=64 over g_out3, tap j=1), relu -------------
__global__ __launch_bounds__(256, 2) void k_e4(const float* __restrict__ w,
                                               const float* __restrict__ bias) {
    const int c0 = blockIdx.y * 16;
    const int b  = (blockIdx.x * 256 + threadIdx.x) * 4;
    __shared__ float ws[64][16];
    for (int idx = threadIdx.x; idx < 64 * 16; idx += 256) {
        int k = idx >> 4, cc = idx & 15;
        ws[k][cc] = w[((size_t)(c0 + cc) * 64 + k) * 3 + 1];
    }
    u64 acc[8][4];
    init_bias(acc, bias, c0);
    __syncthreads();
    gemm_core<64>(ws, g_out3, b, acc);
#pragma unroll
    for (int m = 0; m < 8; m++) {
        int c = c0 + 2 * m;
        *reinterpret_cast<float4*>(&g_out4[(size_t)c * B_ + b])       = relu4(lo4(acc[m]));
        *reinterpret_cast<float4*>(&g_out4[(size_t)(c + 1) * B_ + b]) = relu4(hi4(acc[m]));
    }
}

// ---------------- K6: LSTM gates (GEMM K=128 over g_out4) -------------------
__global__ __launch_bounds__(256, 2) void k_gates(const float* __restrict__ w_ih,
                                                  const float* __restrict__ b_ih,
                                                  const float* __restrict__ b_hh) {
    const int g0 = blockIdx.y * 16;
    const int b  = (blockIdx.x * 256 + threadIdx.x) * 4;
    __shared__ float ws[128][16];
    for (int idx = threadIdx.x; idx < 128 * 16; idx += 256) {
        int k = idx >> 4, cc = idx & 15;
        ws[k][cc] = w_ih[(size_t)(g0 + cc) * 128 + k];
    }
    u64 acc[8][4];
#pragma unroll
    for (int m = 0; m < 8; m++) {
        u64 bv = pack2(b_ih[g0 + 2 * m] + b_hh[g0 + 2 * m],
                       b_ih[g0 + 2 * m + 1] + b_hh[g0 + 2 * m + 1]);
#pragma unroll
        for (int p = 0; p < 4; p++) acc[m][p] = bv;
    }
    __syncthreads();
    gemm_core<128>(ws, g_out4, b, acc);
#pragma unroll
    for (int m = 0; m < 8; m++) {
        int g = g0 + 2 * m;
        *reinterpret_cast<float4*>(&g_gates[(size_t)g * B_ + b])       = lo4(acc[m]);
        *reinterpret_cast<float4*>(&g_gates[(size_t)(g + 1) * B_ + b]) = hi4(acc[m]);
    }
}

// ---------------- K7: LSTM pointwise (h0=c0=0) + decoder + sigmoid ----------
__device__ __forceinline__ float sigf(float x) { return 1.f / (1.f + expf(-x)); }

__global__ __launch_bounds__(256) void k_head(const float* __restrict__ dec_w,
                                              const float* __restrict__ dec_b,
                                              float* __restrict__ out) {
    const int b = (blockIdx.x * 256 + threadIdx.x) * 2;
    __shared__ float wd[128];
    if (threadIdx.x < 128) wd[threadIdx.x] = dec_w[threadIdx.x];
    __syncthreads();
    float d0 = dec_b[0], d1 = d0;
    for (int c = 0; c < 128; c++) {
        u64 ig = ld2(&g_gates[(size_t)(      c) * B_ + b]);
        u64 gg = ld2(&g_gates[(size_t)(256 + c) * B_ + b]);
        u64 og = ld2(&g_gates[(size_t)(384 + c) * B_ + b]);
        float wc = wd[c];
        float cA = sigf(lo32(ig)) * tanhf(lo32(gg));
        float hA = sigf(lo32(og)) * tanhf(cA);
        d0 += fmaxf(hA, 0.f) * wc;
        float cB = sigf(hi32(ig)) * tanhf(hi32(gg));
        float hB = sigf(hi32(og)) * tanhf(cB);
        d1 += fmaxf(hB, 0.f) * wc;
    }
    st2(&out[b], pack2(sigf(d0), sigf(d1)));
}

// ---------------- launch -----------------------------------------------------
extern "C" void kernel_launch(void* const* d_in, const int* in_sizes, int n_in,
                              void* d_out, int out_size) {
    const float* data   = (const float*)d_in[0];
    // d_in[1] = sr (16000 -> context 64, baked in)
    const float* stft_w = (const float*)d_in[2];
    const float* e1_w   = (const float*)d_in[3];
    const float* e1_b   = (const float*)d_in[4];
    const float* e2_w   = (const float*)d_in[5];
    const float* e2_b   = (const float*)d_in[6];
    const float* e3_w   = (const float*)d_in[7];
    const float* e3_b   = (const float*)d_in[8];
    const float* e4_w   = (const float*)d_in[9];
    const float* e4_b   = (const float*)d_in[10];
    const float* w_ih   = (const float*)d_in[11];
    // d_in[12] = w_hh (dead: h0 == 0)
    const float* b_ih   = (const float*)d_in[13];
    const float* b_hh   = (const float*)d_in[14];
    const float* dec_w  = (const float*)d_in[15];
    const float* dec_b  = (const float*)d_in[16];
    float* out = (float*)d_out;

    dim3 blk(256);
    const int GX = B_ / 1024;                 // 64 blocks over batch (4/thread)
    k_transpose<<<dim3(B_ / 32, 16), dim3(32, 8)>>>(data);
    k_stft     <<<dim3(GX, 17, 4), blk>>>(stft_w);   // 17*8 >= 129 freqs
    k_e1       <<<dim3(GX, 8, 4),  blk>>>(e1_w, e1_b);
    k_e2       <<<dim3(GX, 4, 2),  blk>>>(e2_w, e2_b);
    k_e3       <<<dim3(GX, 4),     blk>>>(e3_w, e3_b);
    k_e4       <<<dim3(GX, 8),     blk>>>(e4_w, e4_b);
    k_gates    <<<dim3(GX, 32),    blk>>>(w_ih, b_ih, b_hh);
    k_head     <<<dim3(B_ / 512),  dim3(256)>>>(dec_w, dec_b, out);
}